// round 16
// baseline (speedup 1.0000x reference)
#include <cuda_runtime.h>
#include <cstdint>

#define BATCH 8
#define SEQ 2048
#define DIM 1024
#define M_TOTAL (BATCH * SEQ)

// GEMM: warp-specialized, 576 threads (16 consumer warps + 2 producer warps)
#define BM 128
#define BN 128
#define BK 64
#define KTILES (DIM / BK)        // 16
#define LDT 68                   // padded smem row (floats); LDSM phases conflict-free
#define STAGEF ((BM + BN) * LDT) // floats per stage (A tile + B tile) = 17408
#define NSTAGES 3
#define THREADS 576
#define NCONS 512                // consumer threads
// smem: [0,24) full mbarriers, [32,56) empty mbarriers, [64,...) stage data
#define SMEM_DATA 64
#define SMEM_BYTES (SMEM_DATA + NSTAGES * STAGEF * 4)   // 208960

// scan chunking
#define CHUNKS 16
#define CLEN (SEQ / CHUNKS)      // 128

// -------------------- scratch (static device globals, no alloc) ------------
__device__ float g_u[(size_t)M_TOTAL * DIM];   // u, then h (tf32-rounded) in place
__device__ float g_x[(size_t)M_TOTAL * DIM];   // tf32-rounded x
__device__ float g_Br[DIM * DIM];              // tf32-rounded B
__device__ float g_Wr[DIM * DIM];              // tf32-rounded W
__device__ float g_carry[BATCH * CHUNKS * DIM];

// -------------------- helpers ----------------------------------------------
__device__ __forceinline__ uint32_t smem_u32(const void* p) {
    uint32_t a;
    asm("{ .reg .u64 t; cvta.to.shared.u64 t, %1; cvt.u32.u64 %0, t; }" : "=r"(a) : "l"(p));
    return a;
}
__device__ __forceinline__ float rtf32(float x) {
    uint32_t r;
    asm("cvt.rna.tf32.f32 %0, %1;" : "=r"(r) : "f"(x));
    return __uint_as_float(r);
}
#define CP_ASYNC16(dst, src) \
    asm volatile("cp.async.cg.shared.global [%0], [%1], 16;" :: "r"(dst), "l"(src))

#define MBAR_INIT(addr, cnt) \
    asm volatile("mbarrier.init.shared.b64 [%0], %1;" :: "r"(addr), "r"(cnt) : "memory")

#define MBAR_ARRIVE(addr) \
    asm volatile("mbarrier.arrive.shared.b64 _, [%0];" :: "r"(addr) : "memory")

#define CP_ASYNC_MBAR_ARRIVE(addr) \
    asm volatile("cp.async.mbarrier.arrive.noinc.shared.b64 [%0];" :: "r"(addr) : "memory")

#define MBAR_WAIT(addr, parity) do {                                            \
    asm volatile("{\n\t.reg .pred P1;\n\t"                                      \
        "WL_%=:\n\t"                                                            \
        "mbarrier.try_wait.parity.shared.b64 P1, [%0], %1, 0x989680;\n\t"       \
        "@P1 bra.uni WD_%=;\n\t"                                                \
        "bra.uni WL_%=;\n\t"                                                    \
        "WD_%=:\n\t}"                                                           \
        :: "r"(addr), "r"(parity) : "memory");                                  \
} while (0)

__device__ __forceinline__ void ldsm4(uint32_t& r0, uint32_t& r1, uint32_t& r2,
                                      uint32_t& r3, uint32_t addr) {
    asm volatile("ldmatrix.sync.aligned.m8n8.x4.shared.b16 {%0,%1,%2,%3}, [%4];"
                 : "=r"(r0), "=r"(r1), "=r"(r2), "=r"(r3) : "r"(addr));
}

__device__ __forceinline__ void mma_tf32(float* d, const uint32_t* a, const uint32_t* b) {
    asm volatile(
        "mma.sync.aligned.m16n8k8.row.col.f32.tf32.tf32.f32 "
        "{%0,%1,%2,%3}, {%4,%5,%6,%7}, {%8,%9}, {%0,%1,%2,%3};"
        : "+f"(d[0]), "+f"(d[1]), "+f"(d[2]), "+f"(d[3])
        : "r"(a[0]), "r"(a[1]), "r"(a[2]), "r"(a[3]), "r"(b[0]), "r"(b[1]));
}

// -------------------- warp-specialized tf32 mma.sync GEMM -------------------
// C[m,n] = sum_k A[m,k]*B[n,k] (+bias[n]). A: MxK row-major, B: NxK row-major.
// Inputs pre-rounded to tf32. BK=64: 16 k-tiles, 8 ks-steps per mbarrier wait.
__global__ void __launch_bounds__(THREADS, 1)
gemm_tf32mma(const float* __restrict__ A, const float* __restrict__ Bm,
             const float* __restrict__ bias, float* __restrict__ C,
             int add_bias)
{
    extern __shared__ float sm[];
    const uint32_t sb = smem_u32(sm);
    const int tid = threadIdx.x;
    const int wid = tid >> 5, lid = tid & 31;
    const int bm = blockIdx.y * BM, bn = blockIdx.x * BN;

    if (tid == 0) {
#pragma unroll
        for (int s = 0; s < NSTAGES; s++) {
            MBAR_INIT(sb + s * 8, 64);        // full: 64 producer-thread async arrives
            MBAR_INIT(sb + 32 + s * 8, 16);   // empty: 16 consumer-warp arrives
        }
    }
    __syncthreads();   // one-time: mbarriers visible

    if (wid >= 16) {
        // ---------------- producer: 2 warps, 64 threads ----------------
        const int ptid = tid - NCONS;   // 0..63
        for (int j = 0; j < KTILES; j++) {
            const int s = j % NSTAGES;
            const int f = j / NSTAGES;            // fill number of this stage
            if (j >= NSTAGES)                     // wait consumers done with fill f-1
                MBAR_WAIT(sb + 32 + s * 8, (f - 1) & 1);
            const uint32_t dst = sb + SMEM_DATA + (uint32_t)(s * STAGEF) * 4u;
            const float* Ag = A + (size_t)bm * DIM + j * BK;
            const float* Bg = Bm + (size_t)bn * DIM + j * BK;
#pragma unroll
            for (int it = 0; it < 64; it++) {
                const int idx = ptid + it * 64;          // 0..4095
                const int r = idx >> 4, c = idx & 15;    // 256 rows x 16 chunks of 16B
                const float* src = (r < 128) ? (Ag + (size_t)r * DIM + c * 4)
                                             : (Bg + (size_t)(r - 128) * DIM + c * 4);
                CP_ASYNC16(dst + (uint32_t)(r * LDT + c * 4) * 4u, src);
            }
            CP_ASYNC_MBAR_ARRIVE(sb + s * 8);  // arrive full[s] when copies land
        }
        return;
    }

    // ---------------- consumer: 16 warps, 32x32 tiles ----------------
    const int g = lid >> 2, tg = lid & 3;
    const int warp_m = wid & 3;                 // 0..3 (32 rows)
    const int warp_n = wid >> 2;                // 0..3 (32 cols)

    // ldmatrix per-lane source rows/cols
    const int laneRowA = lid & 15;
    const int laneColA = (lid >> 4) << 2;
    const int laneRowB = (lid & 7) + ((lid >> 4) << 3);
    const int laneColB = ((lid >> 3) & 1) << 2;

    const uint32_t aoff = (uint32_t)((warp_m * 32 + laneRowA) * LDT + laneColA) * 4u;
    const uint32_t boff = (uint32_t)((BM + warp_n * 32 + laneRowB) * LDT + laneColB) * 4u;

    float acc[2][4][4];
#pragma unroll
    for (int mi = 0; mi < 2; mi++)
#pragma unroll
        for (int ni = 0; ni < 4; ni++)
#pragma unroll
            for (int q = 0; q < 4; q++) acc[mi][ni][q] = 0.0f;

    for (int j = 0; j < KTILES; j++) {
        const int s = j % NSTAGES;
        MBAR_WAIT(sb + s * 8, (j / NSTAGES) & 1);   // full[s]

        const uint32_t stg = sb + SMEM_DATA + (uint32_t)(s * STAGEF) * 4u;
        const uint32_t sa = stg + aoff;
        const uint32_t sb2 = stg + boff;

#pragma unroll
        for (int ks = 0; ks < 8; ks++) {
            const uint32_t kb = (uint32_t)(ks * 8) * 4u;
            uint32_t a[2][4], b[4][2];
#pragma unroll
            for (int mi = 0; mi < 2; mi++)
                ldsm4(a[mi][0], a[mi][1], a[mi][2], a[mi][3],
                      sa + kb + (uint32_t)(mi * 16 * LDT) * 4u);
            ldsm4(b[0][0], b[0][1], b[1][0], b[1][1], sb2 + kb);
            ldsm4(b[2][0], b[2][1], b[3][0], b[3][1],
                  sb2 + kb + (uint32_t)(16 * LDT) * 4u);
#pragma unroll
            for (int mi = 0; mi < 2; mi++)
#pragma unroll
                for (int ni = 0; ni < 4; ni++)
                    mma_tf32(acc[mi][ni], a[mi], b[ni]);
        }
        __syncwarp();
        if (lid == 0) MBAR_ARRIVE(sb + 32 + s * 8);   // empty[s]
    }

    // ---- epilogue ----
#pragma unroll
    for (int mi = 0; mi < 2; mi++) {
        const int r0 = bm + warp_m * 32 + mi * 16 + g;
#pragma unroll
        for (int ni = 0; ni < 4; ni++) {
            const int cc = bn + warp_n * 32 + ni * 8 + 2 * tg;
            float2 v0 = make_float2(acc[mi][ni][0], acc[mi][ni][1]);
            float2 v1 = make_float2(acc[mi][ni][2], acc[mi][ni][3]);
            if (add_bias) {
                const float b0 = bias[cc], b1 = bias[cc + 1];
                v0.x += b0; v0.y += b1;
                v1.x += b0; v1.y += b1;
            }
            *reinterpret_cast<float2*>(&C[(size_t)r0 * DIM + cc]) = v0;
            *reinterpret_cast<float2*>(&C[(size_t)(r0 + 8) * DIM + cc]) = v1;
        }
    }
}

// -------------------- tf32 rounding prepass --------------------------------
__global__ void __launch_bounds__(256)
round_tf32_kernel(const float4* __restrict__ in, float4* __restrict__ out, int n4)
{
    int i = blockIdx.x * blockDim.x + threadIdx.x;
    if (i < n4) {
        float4 v = in[i];
        v.x = rtf32(v.x); v.y = rtf32(v.y); v.z = rtf32(v.z); v.w = rtf32(v.w);
        out[i] = v;
    }
}

// -------------------- chunked diagonal scan (in place on g_u) --------------
__global__ void __launch_bounds__(256)
scan_carry(const float* __restrict__ Avec)
{
    const int idx = blockIdx.x * blockDim.x + threadIdx.x;  // 131072
    const int n = idx & (DIM - 1);
    const int ch = (idx >> 10) & (CHUNKS - 1);
    const int b = idx >> 14;
    const float a = Avec[n];
    const float* u = g_u + ((size_t)b * SEQ + (size_t)ch * CLEN) * DIM + n;
    float h = 0.0f;
#pragma unroll 8
    for (int t = 0; t < CLEN; t++) h = fmaf(a, h, u[(size_t)t * DIM]);
    g_carry[idx] = h;
}

// prefix from carries (<=15 L2-resident reads), replay, store tf32-rounded h
__global__ void __launch_bounds__(256)
scan_apply(const float* __restrict__ Avec)
{
    const int idx = blockIdx.x * blockDim.x + threadIdx.x;  // 131072
    const int n = idx & (DIM - 1);
    const int ch = (idx >> 10) & (CHUNKS - 1);
    const int b = idx >> 14;
    const float a = Avec[n];

    float aL = a;
#pragma unroll
    for (int s = 0; s < 7; s++) aL *= aL;   // a^128

    float h = 0.0f;  // prefix entering this chunk
    for (int i = 0; i < ch; i++)
        h = fmaf(aL, h, g_carry[(b * CHUNKS + i) * DIM + n]);

    float* u = g_u + ((size_t)b * SEQ + (size_t)ch * CLEN) * DIM + n;
#pragma unroll 8
    for (int t = 0; t < CLEN; t++) {
        h = fmaf(a, h, u[(size_t)t * DIM]);
        u[(size_t)t * DIM] = rtf32(h);
    }
}

// -------------------- launch -----------------------------------------------
extern "C" void kernel_launch(void* const* d_in, const int* in_sizes, int n_in,
                              void* d_out, int out_size)
{
    const float* x    = (const float*)d_in[0];
    const float* Avec = (const float*)d_in[1];
    const float* Bmat = (const float*)d_in[2];
    const float* Wmat = (const float*)d_in[3];
    const float* bias = (const float*)d_in[4];
    float* out = (float*)d_out;

    float *u, *xr, *Br, *Wr;
    cudaGetSymbolAddress((void**)&u, g_u);
    cudaGetSymbolAddress((void**)&xr, g_x);
    cudaGetSymbolAddress((void**)&Br, g_Br);
    cudaGetSymbolAddress((void**)&Wr, g_Wr);

    cudaFuncSetAttribute(gemm_tf32mma, cudaFuncAttributeMaxDynamicSharedMemorySize, SMEM_BYTES);

    // pre-round inputs to tf32 (rna): keeps cvt out of GEMM hot loops
    const int nx4 = M_TOTAL * DIM / 4;
    const int nw4 = DIM * DIM / 4;
    round_tf32_kernel<<<(nx4 + 255) / 256, 256>>>((const float4*)x, (float4*)xr, nx4);
    round_tf32_kernel<<<(nw4 + 255) / 256, 256>>>((const float4*)Bmat, (float4*)Br, nw4);
    round_tf32_kernel<<<(nw4 + 255) / 256, 256>>>((const float4*)Wmat, (float4*)Wr, nw4);

    dim3 grid(DIM / BN, M_TOTAL / BM);  // (8, 128)

    // u = x_r @ B_r^T
    gemm_tf32mma<<<grid, THREADS, SMEM_BYTES>>>(xr, Br, nullptr, u, 0);

    // h_t = a h_{t-1} + u_t, chunked, in place; h stored tf32-rounded
    scan_carry<<<(BATCH * CHUNKS * DIM) / 256, 256>>>(Avec);
    scan_apply<<<(BATCH * CHUNKS * DIM) / 256, 256>>>(Avec);

    // y = h_r @ W_r^T + b
    gemm_tf32mma<<<grid, THREADS, SMEM_BYTES>>>(u, Wr, bias, out, 1);
}

// round 17
// speedup vs baseline: 1.0155x; 1.0155x over previous
#include <cuda_runtime.h>
#include <cstdint>

#define BATCH 8
#define SEQ 2048
#define DIM 1024
#define M_TOTAL (BATCH * SEQ)

// GEMM: warp-specialized, 320 threads (8 consumer warps + 2 producer warps), occ 2
#define BM 128
#define BN 64
#define BK 32
#define KTILES (DIM / BK)        // 32
#define LDT 36                   // padded smem row (floats); LDSM phases conflict-free
#define STAGEF ((BM + BN) * LDT) // floats per stage = 6912
#define NSTAGES 3
#define THREADS 320
#define NCONS 256                // consumer threads (8 warps)
// smem: [0,24) full mbarriers, [32,56) empty mbarriers, [64,...) stage data
#define SMEM_DATA 64
#define SMEM_BYTES (SMEM_DATA + NSTAGES * STAGEF * 4)   // 83008 -> 2 CTAs/SM

// scan chunking
#define CHUNKS 16
#define CLEN (SEQ / CHUNKS)      // 128

// -------------------- scratch (static device globals, no alloc) ------------
__device__ float g_u[(size_t)M_TOTAL * DIM];   // u, then h (tf32-rounded) in place
__device__ float g_x[(size_t)M_TOTAL * DIM];   // tf32-rounded x
__device__ float g_Br[DIM * DIM];              // tf32-rounded B
__device__ float g_Wr[DIM * DIM];              // tf32-rounded W
__device__ float g_carry[BATCH * CHUNKS * DIM];

// -------------------- helpers ----------------------------------------------
__device__ __forceinline__ uint32_t smem_u32(const void* p) {
    uint32_t a;
    asm("{ .reg .u64 t; cvta.to.shared.u64 t, %1; cvt.u32.u64 %0, t; }" : "=r"(a) : "l"(p));
    return a;
}
__device__ __forceinline__ float rtf32(float x) {
    uint32_t r;
    asm("cvt.rna.tf32.f32 %0, %1;" : "=r"(r) : "f"(x));
    return __uint_as_float(r);
}
#define CP_ASYNC16(dst, src) \
    asm volatile("cp.async.cg.shared.global [%0], [%1], 16;" :: "r"(dst), "l"(src))

#define MBAR_INIT(addr, cnt) \
    asm volatile("mbarrier.init.shared.b64 [%0], %1;" :: "r"(addr), "r"(cnt) : "memory")

#define MBAR_ARRIVE(addr) \
    asm volatile("mbarrier.arrive.shared.b64 _, [%0];" :: "r"(addr) : "memory")

#define CP_ASYNC_MBAR_ARRIVE(addr) \
    asm volatile("cp.async.mbarrier.arrive.noinc.shared.b64 [%0];" :: "r"(addr) : "memory")

#define MBAR_WAIT(addr, parity) do {                                            \
    asm volatile("{\n\t.reg .pred P1;\n\t"                                      \
        "WL_%=:\n\t"                                                            \
        "mbarrier.try_wait.parity.shared.b64 P1, [%0], %1, 0x989680;\n\t"       \
        "@P1 bra.uni WD_%=;\n\t"                                                \
        "bra.uni WL_%=;\n\t"                                                    \
        "WD_%=:\n\t}"                                                           \
        :: "r"(addr), "r"(parity) : "memory");                                  \
} while (0)

__device__ __forceinline__ void ldsm4(uint32_t& r0, uint32_t& r1, uint32_t& r2,
                                      uint32_t& r3, uint32_t addr) {
    asm volatile("ldmatrix.sync.aligned.m8n8.x4.shared.b16 {%0,%1,%2,%3}, [%4];"
                 : "=r"(r0), "=r"(r1), "=r"(r2), "=r"(r3) : "r"(addr));
}

__device__ __forceinline__ void mma_tf32(float* d, const uint32_t* a, const uint32_t* b) {
    asm volatile(
        "mma.sync.aligned.m16n8k8.row.col.f32.tf32.tf32.f32 "
        "{%0,%1,%2,%3}, {%4,%5,%6,%7}, {%8,%9}, {%0,%1,%2,%3};"
        : "+f"(d[0]), "+f"(d[1]), "+f"(d[2]), "+f"(d[3])
        : "r"(a[0]), "r"(a[1]), "r"(a[2]), "r"(a[3]), "r"(b[0]), "r"(b[1]));
}

// -------------------- warp-specialized tf32 mma.sync GEMM, occ 2 ------------
// C[m,n] = sum_k A[m,k]*B[n,k] (+bias[n]). A: MxK row-major, B: NxK row-major.
// Inputs pre-rounded to tf32. Two CTAs/SM decorrelate pipeline stalls.
__global__ void __launch_bounds__(THREADS, 2)
gemm_tf32mma(const float* __restrict__ A, const float* __restrict__ Bm,
             const float* __restrict__ bias, float* __restrict__ C,
             int add_bias)
{
    extern __shared__ float sm[];
    const uint32_t sb = smem_u32(sm);
    const int tid = threadIdx.x;
    const int wid = tid >> 5, lid = tid & 31;
    const int bm = blockIdx.y * BM, bn = blockIdx.x * BN;

    if (tid == 0) {
#pragma unroll
        for (int s = 0; s < NSTAGES; s++) {
            MBAR_INIT(sb + s * 8, 64);        // full: 64 producer-thread async arrives
            MBAR_INIT(sb + 32 + s * 8, 8);    // empty: 8 consumer-warp arrives
        }
    }
    __syncthreads();   // one-time: mbarriers visible

    if (wid >= 8) {
        // ---------------- producer: 2 warps, 64 threads ----------------
        const int ptid = tid - NCONS;   // 0..63
        for (int j = 0; j < KTILES; j++) {
            const int s = j % NSTAGES;
            const int f = j / NSTAGES;            // fill number of this stage
            if (j >= NSTAGES)                     // wait consumers done with fill f-1
                MBAR_WAIT(sb + 32 + s * 8, (f - 1) & 1);
            const uint32_t dst = sb + SMEM_DATA + (uint32_t)(s * STAGEF) * 4u;
            const float* Ag = A + (size_t)bm * DIM + j * BK;
            const float* Bg = Bm + (size_t)bn * DIM + j * BK;
#pragma unroll
            for (int it = 0; it < 24; it++) {
                const int idx = ptid + it * 64;          // 0..1535
                const int r = idx >> 3, c = idx & 7;     // 192 rows x 8 chunks of 16B
                const float* src = (r < BM) ? (Ag + (size_t)r * DIM + c * 4)
                                            : (Bg + (size_t)(r - BM) * DIM + c * 4);
                CP_ASYNC16(dst + (uint32_t)(r * LDT + c * 4) * 4u, src);
            }
            CP_ASYNC_MBAR_ARRIVE(sb + s * 8);  // arrive full[s] when copies land
        }
        return;
    }

    // ---------------- consumer: 8 warps, 32x32 tiles (4 x 2 grid) -----------
    const int g = lid >> 2, tg = lid & 3;
    const int warp_m = wid & 3;                 // 0..3 (32 rows)
    const int warp_n = wid >> 2;                // 0..1 (32 cols)

    // ldmatrix per-lane source rows/cols
    const int laneRowA = lid & 15;
    const int laneColA = (lid >> 4) << 2;
    const int laneRowB = (lid & 7) + ((lid >> 4) << 3);
    const int laneColB = ((lid >> 3) & 1) << 2;

    const uint32_t aoff = (uint32_t)((warp_m * 32 + laneRowA) * LDT + laneColA) * 4u;
    const uint32_t boff = (uint32_t)((BM + warp_n * 32 + laneRowB) * LDT + laneColB) * 4u;

    float acc[2][4][4];
#pragma unroll
    for (int mi = 0; mi < 2; mi++)
#pragma unroll
        for (int ni = 0; ni < 4; ni++)
#pragma unroll
            for (int q = 0; q < 4; q++) acc[mi][ni][q] = 0.0f;

    for (int j = 0; j < KTILES; j++) {
        const int s = j % NSTAGES;
        MBAR_WAIT(sb + s * 8, (j / NSTAGES) & 1);   // full[s]

        const uint32_t stg = sb + SMEM_DATA + (uint32_t)(s * STAGEF) * 4u;
        const uint32_t sa = stg + aoff;
        const uint32_t sb2 = stg + boff;

#pragma unroll
        for (int ks = 0; ks < 4; ks++) {
            const uint32_t kb = (uint32_t)(ks * 8) * 4u;
            uint32_t a[2][4], b[4][2];
#pragma unroll
            for (int mi = 0; mi < 2; mi++)
                ldsm4(a[mi][0], a[mi][1], a[mi][2], a[mi][3],
                      sa + kb + (uint32_t)(mi * 16 * LDT) * 4u);
            ldsm4(b[0][0], b[0][1], b[1][0], b[1][1], sb2 + kb);
            ldsm4(b[2][0], b[2][1], b[3][0], b[3][1],
                  sb2 + kb + (uint32_t)(16 * LDT) * 4u);
#pragma unroll
            for (int mi = 0; mi < 2; mi++)
#pragma unroll
                for (int ni = 0; ni < 4; ni++)
                    mma_tf32(acc[mi][ni], a[mi], b[ni]);
        }
        __syncwarp();
        if (lid == 0) MBAR_ARRIVE(sb + 32 + s * 8);   // empty[s]
    }

    // ---- epilogue ----
#pragma unroll
    for (int mi = 0; mi < 2; mi++) {
        const int r0 = bm + warp_m * 32 + mi * 16 + g;
#pragma unroll
        for (int ni = 0; ni < 4; ni++) {
            const int cc = bn + warp_n * 32 + ni * 8 + 2 * tg;
            float2 v0 = make_float2(acc[mi][ni][0], acc[mi][ni][1]);
            float2 v1 = make_float2(acc[mi][ni][2], acc[mi][ni][3]);
            if (add_bias) {
                const float b0 = bias[cc], b1 = bias[cc + 1];
                v0.x += b0; v0.y += b1;
                v1.x += b0; v1.y += b1;
            }
            *reinterpret_cast<float2*>(&C[(size_t)r0 * DIM + cc]) = v0;
            *reinterpret_cast<float2*>(&C[(size_t)(r0 + 8) * DIM + cc]) = v1;
        }
    }
}

// -------------------- tf32 rounding prepass --------------------------------
__global__ void __launch_bounds__(256)
round_tf32_kernel(const float4* __restrict__ in, float4* __restrict__ out, int n4)
{
    int i = blockIdx.x * blockDim.x + threadIdx.x;
    if (i < n4) {
        float4 v = in[i];
        v.x = rtf32(v.x); v.y = rtf32(v.y); v.z = rtf32(v.z); v.w = rtf32(v.w);
        out[i] = v;
    }
}

// -------------------- chunked diagonal scan (in place on g_u) --------------
__global__ void __launch_bounds__(256)
scan_carry(const float* __restrict__ Avec)
{
    const int idx = blockIdx.x * blockDim.x + threadIdx.x;  // 131072
    const int n = idx & (DIM - 1);
    const int ch = (idx >> 10) & (CHUNKS - 1);
    const int b = idx >> 14;
    const float a = Avec[n];
    const float* u = g_u + ((size_t)b * SEQ + (size_t)ch * CLEN) * DIM + n;
    float h = 0.0f;
#pragma unroll 8
    for (int t = 0; t < CLEN; t++) h = fmaf(a, h, u[(size_t)t * DIM]);
    g_carry[idx] = h;
}

// prefix from carries (<=15 L2-resident reads), replay, store tf32-rounded h
__global__ void __launch_bounds__(256)
scan_apply(const float* __restrict__ Avec)
{
    const int idx = blockIdx.x * blockDim.x + threadIdx.x;  // 131072
    const int n = idx & (DIM - 1);
    const int ch = (idx >> 10) & (CHUNKS - 1);
    const int b = idx >> 14;
    const float a = Avec[n];

    float aL = a;
#pragma unroll
    for (int s = 0; s < 7; s++) aL *= aL;   // a^128

    float h = 0.0f;  // prefix entering this chunk
    for (int i = 0; i < ch; i++)
        h = fmaf(aL, h, g_carry[(b * CHUNKS + i) * DIM + n]);

    float* u = g_u + ((size_t)b * SEQ + (size_t)ch * CLEN) * DIM + n;
#pragma unroll 8
    for (int t = 0; t < CLEN; t++) {
        h = fmaf(a, h, u[(size_t)t * DIM]);
        u[(size_t)t * DIM] = rtf32(h);
    }
}

// -------------------- launch -----------------------------------------------
extern "C" void kernel_launch(void* const* d_in, const int* in_sizes, int n_in,
                              void* d_out, int out_size)
{
    const float* x    = (const float*)d_in[0];
    const float* Avec = (const float*)d_in[1];
    const float* Bmat = (const float*)d_in[2];
    const float* Wmat = (const float*)d_in[3];
    const float* bias = (const float*)d_in[4];
    float* out = (float*)d_out;

    float *u, *xr, *Br, *Wr;
    cudaGetSymbolAddress((void**)&u, g_u);
    cudaGetSymbolAddress((void**)&xr, g_x);
    cudaGetSymbolAddress((void**)&Br, g_Br);
    cudaGetSymbolAddress((void**)&Wr, g_Wr);

    cudaFuncSetAttribute(gemm_tf32mma, cudaFuncAttributeMaxDynamicSharedMemorySize, SMEM_BYTES);

    // pre-round inputs to tf32 (rna): keeps cvt out of GEMM hot loops
    const int nx4 = M_TOTAL * DIM / 4;
    const int nw4 = DIM * DIM / 4;
    round_tf32_kernel<<<(nx4 + 255) / 256, 256>>>((const float4*)x, (float4*)xr, nx4);
    round_tf32_kernel<<<(nw4 + 255) / 256, 256>>>((const float4*)Bmat, (float4*)Br, nw4);
    round_tf32_kernel<<<(nw4 + 255) / 256, 256>>>((const float4*)Wmat, (float4*)Wr, nw4);

    dim3 grid(DIM / BN, M_TOTAL / BM);  // (16, 128)

    // u = x_r @ B_r^T
    gemm_tf32mma<<<grid, THREADS, SMEM_BYTES>>>(xr, Br, nullptr, u, 0);

    // h_t = a h_{t-1} + u_t, chunked, in place; h stored tf32-rounded
    scan_carry<<<(BATCH * CHUNKS * DIM) / 256, 256>>>(Avec);
    scan_apply<<<(BATCH * CHUNKS * DIM) / 256, 256>>>(Avec);

    // y = h_r @ W_r^T + b
    gemm_tf32mma<<<grid, THREADS, SMEM_BYTES>>>(u, Wr, bias, out, 1);
}